// round 13
// baseline (speedup 1.0000x reference)
#include <cuda_runtime.h>

#define H      512
#define NC     64
#define NS     5
#define NQ     15
#define NROWS  1280

__device__ float g_att[NROWS * H];

__device__ __forceinline__ float tanh_approx(float x) {
    float y;
    asm("tanh.approx.f32 %0, %1;" : "=f"(y) : "f"(x));
    return y;
}
__device__ __forceinline__ float rcpf(float x) {
    float y;
    asm("rcp.approx.f32 %0, %1;" : "=f"(y) : "f"(x));
    return y;
}

// ---------------------------------------------------------------------------
// Kernel 1 (FROZEN): g_att = X @ W^T + b
// ---------------------------------------------------------------------------
__global__ __launch_bounds__(128) void gemm_xwt(const float* __restrict__ X,
                                                const float* __restrict__ W,
                                                const float* __restrict__ bias) {
    __shared__ float As[16][68];
    __shared__ float Bs[16][36];
    const int t  = threadIdx.x;
    const int tx = t & 7;
    const int ty = t >> 3;
    const int m0 = blockIdx.y * 64;
    const int n0 = blockIdx.x * 32;
    const int lr = t >> 2;
    const int lk = (t & 3) << 2;

    float acc[4][4] = {};

    for (int kk = 0; kk < H; kk += 16) {
        float4 a0 = *(const float4*)&X[(m0 + lr) * H + kk + lk];
        float4 a1 = *(const float4*)&X[(m0 + lr + 32) * H + kk + lk];
        float4 bv = *(const float4*)&W[(n0 + lr) * H + kk + lk];
        As[lk + 0][lr] = a0.x; As[lk + 1][lr] = a0.y;
        As[lk + 2][lr] = a0.z; As[lk + 3][lr] = a0.w;
        As[lk + 0][lr + 32] = a1.x; As[lk + 1][lr + 32] = a1.y;
        As[lk + 2][lr + 32] = a1.z; As[lk + 3][lr + 32] = a1.w;
        Bs[lk + 0][lr] = bv.x; Bs[lk + 1][lr] = bv.y;
        Bs[lk + 2][lr] = bv.z; Bs[lk + 3][lr] = bv.w;
        __syncthreads();
        #pragma unroll
        for (int k = 0; k < 16; k++) {
            float4 a4 = *(const float4*)&As[k][ty << 2];
            float4 b4 = *(const float4*)&Bs[k][tx << 2];
            float ar[4] = {a4.x, a4.y, a4.z, a4.w};
            float br[4] = {b4.x, b4.y, b4.z, b4.w};
            #pragma unroll
            for (int i = 0; i < 4; i++)
                #pragma unroll
                for (int j = 0; j < 4; j++)
                    acc[i][j] = fmaf(ar[i], br[j], acc[i][j]);
        }
        __syncthreads();
    }

    #pragma unroll
    for (int i = 0; i < 4; i++) {
        const int r = m0 + (ty << 2) + i;
        #pragma unroll
        for (int j = 0; j < 4; j++) {
            const int n = n0 + (tx << 2) + j;
            g_att[r * H + n] = acc[i][j] + bias[n];
        }
    }
}

// ---------------------------------------------------------------------------
// Kernel 2: R12 structure (at MUFU.TANH floor), with half the tanh work
// moved to an FMA-pipe Pade [5/6] (z,w), keeping x,y on MUFU.TANH:
// MUFU cost/elem drops 16 -> 12 cyc. Constants are pinned via SMEM loads
// (Blackwell has no cbank ALU operands; keeps ptxas from rematerializing),
// and the reg cap is 170 (128thr x 3 blocks) so nothing spills.
// ---------------------------------------------------------------------------
__global__ __launch_bounds__(128, 3) void proto_attn(const float* __restrict__ X,
                                                     float* __restrict__ out) {
    const int c    = blockIdx.x;
    const int qb   = blockIdx.y;
    const int t    = threadIdx.x;
    const int warp = t >> 5;
    const int lane = t & 31;

    __shared__ float4 sA[NS * 128];
    __shared__ float4 sS[NS * 128];
    __shared__ float  sC[4];          // Pade constants, pinned via SMEM

    const float4* attv = (const float4*)g_att;
    const float4* xv   = (const float4*)X;

    if (t == 0) {
        sC[0] = 1260.0f;
        sC[1] = 10395.0f;
        sC[2] = 4725.0f;
        sC[3] = 210.0f;
    }
    for (int i = t; i < NS * 128; i += 128) {
        const int s   = i >> 7;
        const int off = i & 127;
        const int row = c * 20 + s;
        sA[i] = attv[row * 128 + off];
        sS[i] = xv[row * 128 + off];
    }
    __syncthreads();

    // Loop-invariant constant registers (ptxas cannot rematerialize SMEM loads)
    const float C1260  = sC[0];
    const float C10395 = sC[1];
    const float C4725  = sC[2];
    const float C210   = sC[3];

    const int qc = qb * 4 + warp;

    for (int j = 0; j < NQ; j++) {
        const int row = qc * 20 + NS + j;
        const float4* qa = attv + row * 128;

        float acc[NS] = {0.f, 0.f, 0.f, 0.f, 0.f};
        #pragma unroll
        for (int i = 0; i < 4; i++) {
            const float4 a = qa[lane + i * 32];
            #pragma unroll
            for (int s = 0; s < NS; s++) {
                const float4 b = sA[s * 128 + lane + i * 32];
                // x,y on the MUFU tanh
                acc[s] += tanh_approx(a.x * b.x);
                acc[s] += tanh_approx(a.y * b.y);
                // z,w on the FMA-pipe Pade [5/6]:
                // tanh(x) ~ x(10395+1260u+21u^2)/(10395+4725u+210u^2+u^3)
                {
                    const float x = a.z * b.z;
                    const float u = x * x;
                    float n = fmaf(u, 21.0f, C1260);     // imm multiplier
                    n = fmaf(n, u, C10395);
                    float dd = fmaf(u + C210, u, C4725);
                    dd = fmaf(dd, u, C10395);
                    acc[s] = fmaf(x * n, rcpf(dd), acc[s]);
                }
                {
                    const float x = a.w * b.w;
                    const float u = x * x;
                    float n = fmaf(u, 21.0f, C1260);
                    n = fmaf(n, u, C10395);
                    float dd = fmaf(u + C210, u, C4725);
                    dd = fmaf(dd, u, C10395);
                    acc[s] = fmaf(x * n, rcpf(dd), acc[s]);
                }
            }
        }
        #pragma unroll
        for (int s = 0; s < NS; s++) {
            #pragma unroll
            for (int o = 16; o > 0; o >>= 1)
                acc[s] += __shfl_xor_sync(0xffffffffu, acc[s], o);
        }

        // softmax over the 5 support scores
        float m = acc[0];
        #pragma unroll
        for (int s = 1; s < NS; s++) m = fmaxf(m, acc[s]);
        float w[NS];
        float sum = 0.f;
        #pragma unroll
        for (int s = 0; s < NS; s++) { w[s] = __expf(acc[s] - m); sum += w[s]; }
        const float inv = __fdividef(1.0f, sum);
        #pragma unroll
        for (int s = 0; s < NS; s++) w[s] *= inv;

        // proto & dist
        const float4* qx = xv + row * 128;
        float d = 0.f;
        #pragma unroll
        for (int i = 0; i < 4; i++) {
            const float4 qv = qx[lane + i * 32];
            float px = 0.f, py = 0.f, pz = 0.f, pw = 0.f;
            #pragma unroll
            for (int s = 0; s < NS; s++) {
                const float4 sv = sS[s * 128 + lane + i * 32];
                px = fmaf(w[s], sv.x, px);
                py = fmaf(w[s], sv.y, py);
                pz = fmaf(w[s], sv.z, pz);
                pw = fmaf(w[s], sv.w, pw);
            }
            const float dx = px - qv.x, dy = py - qv.y;
            const float dz = pz - qv.z, dw = pw - qv.w;
            d += dx * dx + dy * dy + dz * dz + dw * dw;
        }
        #pragma unroll
        for (int o = 16; o > 0; o >>= 1)
            d += __shfl_xor_sync(0xffffffffu, d, o);

        if (lane == 0) {
            const int q = qc * NQ + j;
            out[q * NC + c] = d;
        }
    }
}

extern "C" void kernel_launch(void* const* d_in, const int* in_sizes, int n_in,
                              void* d_out, int out_size) {
    const float* x = (const float*)d_in[0];
    const float* W = (const float*)d_in[1];
    const float* b = (const float*)d_in[2];
    float* out = (float*)d_out;

    gemm_xwt<<<dim3(H / 32, NROWS / 64), 128>>>(x, W, b);
    proto_attn<<<dim3(NC, 16), 128>>>(x, out);
}

// round 14
// speedup vs baseline: 1.3238x; 1.3238x over previous
#include <cuda_runtime.h>

#define H      512
#define NC     64
#define NS     5
#define NQ     15
#define NROWS  1280

__device__ float g_att[NROWS * H];

__device__ __forceinline__ float tanh_approx(float x) {
    float y;
    asm("tanh.approx.f32 %0, %1;" : "=f"(y) : "f"(x));
    return y;
}

// ---------------------------------------------------------------------------
// Kernel 1: g_att = X @ W^T + b
// 64(m) x 32(n) tile, 128 threads, 4x4 micro-tile, BK=32, software-pipelined:
// next tile's global loads are staged in registers during compute, so the
// ~250-cyc L2-hit LDG latency is hidden instead of exposed every iteration.
// ---------------------------------------------------------------------------
__global__ __launch_bounds__(128) void gemm_xwt(const float* __restrict__ X,
                                                const float* __restrict__ W,
                                                const float* __restrict__ bias) {
    __shared__ float As[32][68];   // [k][m] 64 rows (+4 pad)
    __shared__ float Bs[32][36];   // [k][n] 32 rows (+4 pad)
    const int t  = threadIdx.x;
    const int tx = t & 7;          // n: 8 x 4
    const int ty = t >> 3;         // m: 16 x 4
    const int m0 = blockIdx.y * 64;
    const int n0 = blockIdx.x * 32;

    // A tile: 64 rows x 32 k = 512 float4 loads -> 4 per thread
    const int ar_ = t >> 1;            // 0..63 (row), two threads per row
    const int ak_ = (t & 1) << 4;      // k offset 0 or 16 (two float4 each)
    // B tile: 32 rows x 32 k = 256 float4 loads -> 2 per thread
    const int br_ = t >> 2;            // 0..31 (row)
    const int bk_ = (t & 3) << 3;      // k offset 0,8,16,24 (two float4)

    float acc[4][4] = {};

    // Prologue: stage first tile in registers
    float4 a0r = *(const float4*)&X[(m0 + ar_) * H + 0 + ak_];
    float4 a1r = *(const float4*)&X[(m0 + ar_) * H + 0 + ak_ + 4];
    float4 a2r = *(const float4*)&X[(m0 + ar_) * H + 0 + ak_ + 8];
    float4 a3r = *(const float4*)&X[(m0 + ar_) * H + 0 + ak_ + 12];
    float4 b0r = *(const float4*)&W[(n0 + br_) * H + 0 + bk_];
    float4 b1r = *(const float4*)&W[(n0 + br_) * H + 0 + bk_ + 4];

    for (int kk = 0; kk < H; kk += 32) {
        // Store staged registers to smem (transposed)
        As[ak_ +  0][ar_] = a0r.x; As[ak_ +  1][ar_] = a0r.y;
        As[ak_ +  2][ar_] = a0r.z; As[ak_ +  3][ar_] = a0r.w;
        As[ak_ +  4][ar_] = a1r.x; As[ak_ +  5][ar_] = a1r.y;
        As[ak_ +  6][ar_] = a1r.z; As[ak_ +  7][ar_] = a1r.w;
        As[ak_ +  8][ar_] = a2r.x; As[ak_ +  9][ar_] = a2r.y;
        As[ak_ + 10][ar_] = a2r.z; As[ak_ + 11][ar_] = a2r.w;
        As[ak_ + 12][ar_] = a3r.x; As[ak_ + 13][ar_] = a3r.y;
        As[ak_ + 14][ar_] = a3r.z; As[ak_ + 15][ar_] = a3r.w;
        Bs[bk_ + 0][br_] = b0r.x; Bs[bk_ + 1][br_] = b0r.y;
        Bs[bk_ + 2][br_] = b0r.z; Bs[bk_ + 3][br_] = b0r.w;
        Bs[bk_ + 4][br_] = b1r.x; Bs[bk_ + 5][br_] = b1r.y;
        Bs[bk_ + 6][br_] = b1r.z; Bs[bk_ + 7][br_] = b1r.w;
        __syncthreads();

        // Prefetch next tile (latency hidden by the compute below)
        if (kk + 32 < H) {
            const int kn = kk + 32;
            a0r = *(const float4*)&X[(m0 + ar_) * H + kn + ak_];
            a1r = *(const float4*)&X[(m0 + ar_) * H + kn + ak_ + 4];
            a2r = *(const float4*)&X[(m0 + ar_) * H + kn + ak_ + 8];
            a3r = *(const float4*)&X[(m0 + ar_) * H + kn + ak_ + 12];
            b0r = *(const float4*)&W[(n0 + br_) * H + kn + bk_];
            b1r = *(const float4*)&W[(n0 + br_) * H + kn + bk_ + 4];
        }

        #pragma unroll
        for (int k = 0; k < 32; k++) {
            float4 a4 = *(const float4*)&As[k][ty << 2];
            float4 b4 = *(const float4*)&Bs[k][tx << 2];
            float ar[4] = {a4.x, a4.y, a4.z, a4.w};
            float br[4] = {b4.x, b4.y, b4.z, b4.w};
            #pragma unroll
            for (int i = 0; i < 4; i++)
                #pragma unroll
                for (int j = 0; j < 4; j++)
                    acc[i][j] = fmaf(ar[i], br[j], acc[i][j]);
        }
        __syncthreads();
    }

    #pragma unroll
    for (int i = 0; i < 4; i++) {
        const int r = m0 + (ty << 2) + i;
        #pragma unroll
        for (int j = 0; j < 4; j++) {
            const int n = n0 + (tx << 2) + j;
            g_att[r * H + n] = acc[i][j] + bias[n];
        }
    }
}

// ---------------------------------------------------------------------------
// Kernel 2 (FROZEN = R12, measured 63.1us = 100.8% of the MUFU.TANH floor):
// 128-thread blocks, grid (64, 16), plain MUFU tanh.
// ---------------------------------------------------------------------------
__global__ __launch_bounds__(128, 4) void proto_attn(const float* __restrict__ X,
                                                     float* __restrict__ out) {
    const int c    = blockIdx.x;
    const int qb   = blockIdx.y;
    const int t    = threadIdx.x;
    const int warp = t >> 5;
    const int lane = t & 31;

    __shared__ float4 sA[NS * 128];
    __shared__ float4 sS[NS * 128];

    const float4* attv = (const float4*)g_att;
    const float4* xv   = (const float4*)X;

    for (int i = t; i < NS * 128; i += 128) {
        const int s   = i >> 7;
        const int off = i & 127;
        const int row = c * 20 + s;
        sA[i] = attv[row * 128 + off];
        sS[i] = xv[row * 128 + off];
    }
    __syncthreads();

    const int qc = qb * 4 + warp;

    for (int j = 0; j < NQ; j++) {
        const int row = qc * 20 + NS + j;
        const float4* qa = attv + row * 128;

        float acc[NS] = {0.f, 0.f, 0.f, 0.f, 0.f};
        #pragma unroll
        for (int i = 0; i < 4; i++) {
            const float4 a = qa[lane + i * 32];
            #pragma unroll
            for (int s = 0; s < NS; s++) {
                const float4 b = sA[s * 128 + lane + i * 32];
                acc[s] += tanh_approx(a.x * b.x);
                acc[s] += tanh_approx(a.y * b.y);
                acc[s] += tanh_approx(a.z * b.z);
                acc[s] += tanh_approx(a.w * b.w);
            }
        }
        #pragma unroll
        for (int s = 0; s < NS; s++) {
            #pragma unroll
            for (int o = 16; o > 0; o >>= 1)
                acc[s] += __shfl_xor_sync(0xffffffffu, acc[s], o);
        }

        float m = acc[0];
        #pragma unroll
        for (int s = 1; s < NS; s++) m = fmaxf(m, acc[s]);
        float w[NS];
        float sum = 0.f;
        #pragma unroll
        for (int s = 0; s < NS; s++) { w[s] = __expf(acc[s] - m); sum += w[s]; }
        const float inv = __fdividef(1.0f, sum);
        #pragma unroll
        for (int s = 0; s < NS; s++) w[s] *= inv;

        const float4* qx = xv + row * 128;
        float d = 0.f;
        #pragma unroll
        for (int i = 0; i < 4; i++) {
            const float4 qv = qx[lane + i * 32];
            float px = 0.f, py = 0.f, pz = 0.f, pw = 0.f;
            #pragma unroll
            for (int s = 0; s < NS; s++) {
                const float4 sv = sS[s * 128 + lane + i * 32];
                px = fmaf(w[s], sv.x, px);
                py = fmaf(w[s], sv.y, py);
                pz = fmaf(w[s], sv.z, pz);
                pw = fmaf(w[s], sv.w, pw);
            }
            const float dx = px - qv.x, dy = py - qv.y;
            const float dz = pz - qv.z, dw = pw - qv.w;
            d += dx * dx + dy * dy + dz * dz + dw * dw;
        }
        #pragma unroll
        for (int o = 16; o > 0; o >>= 1)
            d += __shfl_xor_sync(0xffffffffu, d, o);

        if (lane == 0) {
            const int q = qc * NQ + j;
            out[q * NC + c] = d;
        }
    }
}

extern "C" void kernel_launch(void* const* d_in, const int* in_sizes, int n_in,
                              void* d_out, int out_size) {
    const float* x = (const float*)d_in[0];
    const float* W = (const float*)d_in[1];
    const float* b = (const float*)d_in[2];
    float* out = (float*)d_out;

    gemm_xwt<<<dim3(H / 32, NROWS / 64), 128>>>(x, W, b);
    proto_attn<<<dim3(NC, 16), 128>>>(x, out);
}

// round 15
// speedup vs baseline: 1.6920x; 1.2781x over previous
#include <cuda_runtime.h>
#include <cstdint>

#define H      512
#define NC     64
#define NS     5
#define NQ     15
#define NROWS  1280

__device__ float g_att[NROWS * H];

__device__ __forceinline__ float tanh_approx(float x) {
    float y;
    asm("tanh.approx.f32 %0, %1;" : "=f"(y) : "f"(x));
    return y;
}

__device__ __forceinline__ float to_tf32(float x) {
    uint32_t r;
    asm("cvt.rna.tf32.f32 %0, %1;" : "=r"(r) : "f"(x));
    return __uint_as_float(r);
}

__device__ __forceinline__ void mma_tf32(float& c0, float& c1, float& c2, float& c3,
                                         float a0, float a1, float a2, float a3,
                                         float b0, float b1) {
    asm volatile(
        "mma.sync.aligned.m16n8k8.row.col.f32.tf32.tf32.f32 "
        "{%0,%1,%2,%3}, {%4,%5,%6,%7}, {%8,%9}, {%0,%1,%2,%3};"
        : "+f"(c0), "+f"(c1), "+f"(c2), "+f"(c3)
        : "r"(__float_as_uint(a0)), "r"(__float_as_uint(a1)),
          "r"(__float_as_uint(a2)), "r"(__float_as_uint(a3)),
          "r"(__float_as_uint(b0)), "r"(__float_as_uint(b1)));
}

// ---------------------------------------------------------------------------
// Kernel 1: g_att = X @ W^T + b via tf32 tensor-core mma.sync.
// Block tile 64(m) x 64(n), 256 threads = 8 warps, each warp 16m x 32n
// (1 m-frag x 4 n-frags). BK=32 (4 k8 steps), SMEM pitch 36 floats ->
// conflict-free fragment LDS. tf32 conversion once at SMEM store.
// Grid (8 n-tiles, 20 m-tiles) = 160 blocks.
// ---------------------------------------------------------------------------
__global__ __launch_bounds__(256) void gemm_xwt(const float* __restrict__ X,
                                                const float* __restrict__ W,
                                                const float* __restrict__ bias) {
    __shared__ float As[64 * 36];   // [m][k], pitch 36
    __shared__ float Bs[64 * 36];   // [n][k], pitch 36
    __shared__ float sb[64];

    const int t     = threadIdx.x;
    const int warp  = t >> 5;
    const int lane  = t & 31;
    const int m0    = blockIdx.y * 64;
    const int n0    = blockIdx.x * 64;
    const int wm    = (warp >> 1) * 16;          // warp m offset within tile
    const int wn    = (warp & 1) * 32;           // warp n offset within tile
    const int group = lane >> 2;                 // 0..7
    const int tid4  = lane & 3;                  // 0..3

    if (t < 64) sb[t] = bias[n0 + t];

    // G->S mapping: 512 float4 per tile, 2 per thread (i = t, t+256)
    const int r0 = t >> 3;            // rows 0..31
    const int c0_ = (t & 7) << 2;     // col offset in floats (0,4,..,28)

    float4 a0r, a1r, b0r, b1r;

    // Prologue: stage first K-slab
    a0r = *(const float4*)&X[(m0 + r0) * H + c0_];
    a1r = *(const float4*)&X[(m0 + r0 + 32) * H + c0_];
    b0r = *(const float4*)&W[(n0 + r0) * H + c0_];
    b1r = *(const float4*)&W[(n0 + r0 + 32) * H + c0_];

    float acc[4][4] = {};   // 4 n-frags x {c0,c1,c2,c3}

    for (int kk = 0; kk < H; kk += 32) {
        // Store staged slab to SMEM (tf32-rounded)
        {
            float* pa0 = &As[r0 * 36 + c0_];
            float* pa1 = &As[(r0 + 32) * 36 + c0_];
            float* pb0 = &Bs[r0 * 36 + c0_];
            float* pb1 = &Bs[(r0 + 32) * 36 + c0_];
            pa0[0] = to_tf32(a0r.x); pa0[1] = to_tf32(a0r.y);
            pa0[2] = to_tf32(a0r.z); pa0[3] = to_tf32(a0r.w);
            pa1[0] = to_tf32(a1r.x); pa1[1] = to_tf32(a1r.y);
            pa1[2] = to_tf32(a1r.z); pa1[3] = to_tf32(a1r.w);
            pb0[0] = to_tf32(b0r.x); pb0[1] = to_tf32(b0r.y);
            pb0[2] = to_tf32(b0r.z); pb0[3] = to_tf32(b0r.w);
            pb1[0] = to_tf32(b1r.x); pb1[1] = to_tf32(b1r.y);
            pb1[2] = to_tf32(b1r.z); pb1[3] = to_tf32(b1r.w);
        }
        __syncthreads();

        // Prefetch next slab
        if (kk + 32 < H) {
            const int kn = kk + 32;
            a0r = *(const float4*)&X[(m0 + r0) * H + kn + c0_];
            a1r = *(const float4*)&X[(m0 + r0 + 32) * H + kn + c0_];
            b0r = *(const float4*)&W[(n0 + r0) * H + kn + c0_];
            b1r = *(const float4*)&W[(n0 + r0 + 32) * H + kn + c0_];
        }

        #pragma unroll
        for (int ks = 0; ks < 32; ks += 8) {
            // A fragment (row-major m16k8)
            const float* ar0 = &As[(wm + group) * 36 + ks + tid4];
            const float* ar1 = &As[(wm + group + 8) * 36 + ks + tid4];
            const float fa0 = ar0[0];
            const float fa1 = ar1[0];
            const float fa2 = ar0[4];
            const float fa3 = ar1[4];
            #pragma unroll
            for (int f = 0; f < 4; f++) {
                // B fragment (col-major k8n8): col(n)=group, row(k)=tid4
                const float* br = &Bs[(wn + f * 8 + group) * 36 + ks + tid4];
                const float fb0 = br[0];
                const float fb1 = br[4];
                mma_tf32(acc[f][0], acc[f][1], acc[f][2], acc[f][3],
                         fa0, fa1, fa2, fa3, fb0, fb1);
            }
        }
        __syncthreads();
    }

    // Epilogue: add bias, store. c0/c1: row=group, cols 2*tid4, 2*tid4+1.
    #pragma unroll
    for (int f = 0; f < 4; f++) {
        const int col = wn + f * 8 + 2 * tid4;
        const float bz0 = sb[col], bz1 = sb[col + 1];
        const int gr0 = m0 + wm + group;
        float2* p0 = (float2*)&g_att[gr0 * H + n0 + col];
        float2* p1 = (float2*)&g_att[(gr0 + 8) * H + n0 + col];
        *p0 = make_float2(acc[f][0] + bz0, acc[f][1] + bz1);
        *p1 = make_float2(acc[f][2] + bz0, acc[f][3] + bz1);
    }
}

// ---------------------------------------------------------------------------
// Kernel 2 (FROZEN = R12/R14, 62.7us = MUFU.TANH floor): 128-thread blocks,
// grid (64, 16), plain MUFU tanh.
// ---------------------------------------------------------------------------
__global__ __launch_bounds__(128, 4) void proto_attn(const float* __restrict__ X,
                                                     float* __restrict__ out) {
    const int c    = blockIdx.x;
    const int qb   = blockIdx.y;
    const int t    = threadIdx.x;
    const int warp = t >> 5;
    const int lane = t & 31;

    __shared__ float4 sA[NS * 128];
    __shared__ float4 sS[NS * 128];

    const float4* attv = (const float4*)g_att;
    const float4* xv   = (const float4*)X;

    for (int i = t; i < NS * 128; i += 128) {
        const int s   = i >> 7;
        const int off = i & 127;
        const int row = c * 20 + s;
        sA[i] = attv[row * 128 + off];
        sS[i] = xv[row * 128 + off];
    }
    __syncthreads();

    const int qc = qb * 4 + warp;

    for (int j = 0; j < NQ; j++) {
        const int row = qc * 20 + NS + j;
        const float4* qa = attv + row * 128;

        float acc[NS] = {0.f, 0.f, 0.f, 0.f, 0.f};
        #pragma unroll
        for (int i = 0; i < 4; i++) {
            const float4 a = qa[lane + i * 32];
            #pragma unroll
            for (int s = 0; s < NS; s++) {
                const float4 b = sA[s * 128 + lane + i * 32];
                acc[s] += tanh_approx(a.x * b.x);
                acc[s] += tanh_approx(a.y * b.y);
                acc[s] += tanh_approx(a.z * b.z);
                acc[s] += tanh_approx(a.w * b.w);
            }
        }
        #pragma unroll
        for (int s = 0; s < NS; s++) {
            #pragma unroll
            for (int o = 16; o > 0; o >>= 1)
                acc[s] += __shfl_xor_sync(0xffffffffu, acc[s], o);
        }

        float m = acc[0];
        #pragma unroll
        for (int s = 1; s < NS; s++) m = fmaxf(m, acc[s]);
        float w[NS];
        float sum = 0.f;
        #pragma unroll
        for (int s = 0; s < NS; s++) { w[s] = __expf(acc[s] - m); sum += w[s]; }
        const float inv = __fdividef(1.0f, sum);
        #pragma unroll
        for (int s = 0; s < NS; s++) w[s] *= inv;

        const float4* qx = xv + row * 128;
        float d = 0.f;
        #pragma unroll
        for (int i = 0; i < 4; i++) {
            const float4 qv = qx[lane + i * 32];
            float px = 0.f, py = 0.f, pz = 0.f, pw = 0.f;
            #pragma unroll
            for (int s = 0; s < NS; s++) {
                const float4 sv = sS[s * 128 + lane + i * 32];
                px = fmaf(w[s], sv.x, px);
                py = fmaf(w[s], sv.y, py);
                pz = fmaf(w[s], sv.z, pz);
                pw = fmaf(w[s], sv.w, pw);
            }
            const float dx = px - qv.x, dy = py - qv.y;
            const float dz = pz - qv.z, dw = pw - qv.w;
            d += dx * dx + dy * dy + dz * dz + dw * dw;
        }
        #pragma unroll
        for (int o = 16; o > 0; o >>= 1)
            d += __shfl_xor_sync(0xffffffffu, d, o);

        if (lane == 0) {
            const int q = qc * NQ + j;
            out[q * NC + c] = d;
        }
    }
}

extern "C" void kernel_launch(void* const* d_in, const int* in_sizes, int n_in,
                              void* d_out, int out_size) {
    const float* x = (const float*)d_in[0];
    const float* W = (const float*)d_in[1];
    const float* b = (const float*)d_in[2];
    float* out = (float*)d_out;

    gemm_xwt<<<dim3(8, 20), 256>>>(x, W, b);
    proto_attn<<<dim3(NC, 16), 128>>>(x, out);
}